// round 3
// baseline (speedup 1.0000x reference)
#include <cuda_runtime.h>
#include <mma.h>
#include <math.h>

using namespace nvcuda;

#define NB   2
#define NN   256
#define NF   64
#define NKF  50
#define NH   4
#define NC   256
#define DCAT 179   // 2F + KF + 1

// scratch (static device memory; allocation-free)
__device__ float g_U[(size_t)NB*NN*NN*NC];   // [bi][j][c'] c'=hd*64+f, full fp32 (134MB)
__device__ float g_hes[NB*NN*NC];            // [bi][c]  c=f*4+hd (original order)

__device__ __forceinline__ float siluf(float v){ return v / (1.f + __expf(-v)); }
__device__ __forceinline__ float tf32r(float x){
    unsigned u; asm("cvt.rna.tf32.f32 %0, %1;" : "=r"(u) : "f"(x));
    return __uint_as_float(u);
}
__device__ __forceinline__ float tanhap(float x){
    float y; asm("tanh.approx.f32 %0, %1;" : "=f"(y) : "f"(x)); return y;
}

// ---------------------------------------------------------------------------
// Kernel A: edge MLP + semantic attention softmax. One block per (b,i),
// thread j handles pair (i,j). Emits g_U (fp32, hd-major) and g_hes.
// ---------------------------------------------------------------------------
__global__ __launch_bounds__(256, 1) void k_edge(
    const float* __restrict__ h,     const float* __restrict__ x,
    const float* __restrict__ W_in,  const float* __restrict__ b_in,
    const float* __restrict__ means, const float* __restrict__ betas,
    const float* __restrict__ W_o1,  const float* __restrict__ b_o1,
    const float* __restrict__ W_o2,  const float* __restrict__ b_o2,
    const float* __restrict__ W_sem, const float* __restrict__ b_sem)
{
    extern __shared__ __align__(32) float sm[];
    float* sh_h  = sm;                 // 256*65
    float* sWin  = sh_h + NN*65;       // 128*50 = 6400
    float* sWo1  = sWin + 128*NKF;     // 179*64 = 11456
    float* sWo2  = sWo1 + DCAT*64;     // 64*64
    float* sWsem = sWo2 + 64*64;       // 256
    float* sbin  = sWsem + 256;        // 50
    float* smean = sbin + NKF;
    float* sbeta = smean + NKF;
    float* sbo1  = sbeta + NKF;        // 64
    float* sbo2  = sbo1 + 64;          // 64
    float* sbsem = sbo2 + 64;          // 4(+4 pad)
    float* sx    = sbsem + 8;          // 768
    float* sLog  = sx + NN*3;          // 1024
    float* sRed  = sLog + 4*NN;        // 16
    // phase-2 aliases (weight region reused after all warps pass the sync)
    float* sHeMat = sWin;              // 256*65 = 16640
    float* sAttS  = sWin + 16640;      // 256*4

    const int t  = threadIdx.x;
    const int bi = blockIdx.x;
    const int b  = bi >> 8;
    const int i  = bi & 255;

    for (int l = t; l < NN*NF;   l += 256) sh_h[(l>>6)*65 + (l&63)] = h[b*NN*NF + l];
    for (int l = t; l < 128*NKF; l += 256) sWin[l] = W_in[l];
    for (int l = t; l < DCAT*64; l += 256) sWo1[l] = W_o1[l];
    for (int l = t; l < 64*64;   l += 256) sWo2[l] = W_o2[l];
    sWsem[t] = W_sem[t];
    if (t < NKF) { sbin[t]=b_in[t]; smean[t]=means[t]; sbeta[t]=betas[t]; }
    if (t < 64)  { sbo1[t]=b_o1[t]; sbo2[t]=b_o2[t]; }
    if (t < 4)   sbsem[t]=b_sem[t];
    for (int l = t; l < NN*3; l += 256) sx[l] = x[b*NN*3 + l];
    __syncthreads();

    const int j = t;
    const float dx = sx[j*3+0]-sx[i*3+0];
    const float dy = sx[j*3+1]-sx[i*3+1];
    const float dz = sx[j*3+2]-sx[i*3+2];
    const float ss = dx*dx + dy*dy + dz*dz;
    const float d  = sqrtf(fmaxf(ss, 0.f) + 1e-5f);

    // --- h1 = h_cat @ W_in + b_in ---
    float h1[NKF];
    #pragma unroll
    for (int k = 0; k < NKF; k++) h1[k] = sbin[k];
    const float* hj = sh_h + j*65;
    const float* hi = sh_h + i*65;
    for (int f = 0; f < NF; f++) {
        const float vj = hj[f], vi = hi[f];
        const float2* rj = (const float2*)(sWin + f*NKF);
        const float2* ri = (const float2*)(sWin + (64+f)*NKF);
        #pragma unroll
        for (int k2 = 0; k2 < NKF/2; k2++) {
            float2 wj = rj[k2], wi = ri[k2];
            h1[2*k2]   += vj*wj.x + vi*wi.x;
            h1[2*k2+1] += vj*wj.y + vi*wi.y;
        }
    }

    // --- rbf * h1 ---
    const float em  = __expf(-d);
    const float cut = (d < 5.f) ? 0.5f*(__cosf(d*0.6283185307179586f)+1.f) : 0.f;
    float rh[NKF];
    #pragma unroll
    for (int k = 0; k < NKF; k++) {
        float dm = em - smean[k];
        rh[k] = cut * __expf(-sbeta[k]*dm*dm) * h1[k];
    }

    // --- tv = silu(concat(z) @ W_o1 + b_o1) ---
    float tv[64];
    #pragma unroll
    for (int k = 0; k < 64; k++) tv[k] = sbo1[k];
    auto acc_row = [&](float val, const float* row) {
        const float4* r4 = (const float4*)row;
        #pragma unroll
        for (int q = 0; q < 16; q++) {
            float4 w = r4[q];
            tv[4*q+0] += val*w.x; tv[4*q+1] += val*w.y;
            tv[4*q+2] += val*w.z; tv[4*q+3] += val*w.w;
        }
    };
    for (int f = 0; f < 64; f++) acc_row(hj[f], sWo1 + f*64);
    for (int f = 0; f < 64; f++) acc_row(hi[f], sWo1 + (64+f)*64);
    #pragma unroll
    for (int k = 0; k < NKF; k++) acc_row(rh[k], sWo1 + (128+k)*64);
    acc_row(d, sWo1 + 178*64);
    #pragma unroll
    for (int k = 0; k < 64; k++) tv[k] = siluf(tv[k]);

    // --- he = tv @ W_o2 + b_o2 ---
    float he[64];
    #pragma unroll
    for (int k = 0; k < 64; k++) he[k] = sbo2[k];
    #pragma unroll
    for (int c = 0; c < 64; c++) {
        const float val = tv[c];
        const float4* r4 = (const float4*)(sWo2 + c*64);
        #pragma unroll
        for (int q = 0; q < 16; q++) {
            float4 w = r4[q];
            he[4*q+0] += val*w.x; he[4*q+1] += val*w.y;
            he[4*q+2] += val*w.z; he[4*q+3] += val*w.w;
        }
    }

    // --- semantic logits + celu(alpha=2) + self-mask ---
    float l0=sbsem[0], l1=sbsem[1], l2=sbsem[2], l3=sbsem[3];
    #pragma unroll
    for (int f = 0; f < 64; f++) {
        const float v4 = he[f];
        l0 += v4*sWsem[f*4+0]; l1 += v4*sWsem[f*4+1];
        l2 += v4*sWsem[f*4+2]; l3 += v4*sWsem[f*4+3];
    }
    float lg[4] = {l0, l1, l2, l3};
    #pragma unroll
    for (int hd = 0; hd < 4; hd++) {
        float a = lg[hd];
        a = (a > 0.f) ? a : 2.f*(__expf(0.5f*a) - 1.f);
        if (j == i) a -= 1e5f;
        lg[hd] = a;
    }

    __syncthreads();   // all warps done with weight region; begin aliasing
    #pragma unroll
    for (int f = 0; f < 64; f++) sHeMat[j*65 + f] = he[f];
    #pragma unroll
    for (int hd = 0; hd < 4; hd++) sLog[hd*NN + j] = lg[hd];
    __syncthreads();

    // --- softmax over j, one warp per head ---
    const int wp = t >> 5, lane = t & 31;
    if (wp < 4) {
        float m = -1e30f;
        for (int q = 0; q < 8; q++) m = fmaxf(m, sLog[wp*NN + lane + 32*q]);
        #pragma unroll
        for (int o = 16; o; o >>= 1) m = fmaxf(m, __shfl_xor_sync(~0u, m, o));
        float s = 0.f;
        for (int q = 0; q < 8; q++) s += __expf(sLog[wp*NN + lane + 32*q] - m);
        #pragma unroll
        for (int o = 16; o; o >>= 1) s += __shfl_xor_sync(~0u, s, o);
        if (lane == 0) { sRed[wp*2] = m; sRed[wp*2+1] = s; }
    }
    __syncthreads();

    float att4[4];
    #pragma unroll
    for (int hd = 0; hd < 4; hd++) {
        att4[hd] = __expf(sLog[hd*NN + j] - sRed[hd*2]) / sRed[hd*2+1];
        sAttS[j*4 + hd] = att4[hd];
    }
    // write U row: c' = hd*64 + f, full fp32
    {
        float* ub = g_U + ((size_t)bi*NN + j)*NC;
        #pragma unroll
        for (int c4 = 0; c4 < 64; c4++) {
            const int i0 = 4*c4;
            float4 u;
            u.x = att4[(i0+0)>>6] * he[(i0+0)&63];
            u.y = att4[(i0+1)>>6] * he[(i0+1)&63];
            u.z = att4[(i0+2)>>6] * he[(i0+2)&63];
            u.w = att4[(i0+3)>>6] * he[(i0+3)&63];
            *(float4*)(ub + i0) = u;
        }
    }
    __syncthreads();

    // --- h_e column sums (original c order: c = f*4 + hd) ---
    {
        const int f = t >> 2, hd = t & 3;
        float s = 0.f;
        for (int jj = 0; jj < NN; jj++) s += sHeMat[jj*65 + f] * sAttS[jj*4 + hd];
        g_hes[bi*NC + t] = s;
    }
}

// ---------------------------------------------------------------------------
// Kernel B: 3xTF32 wmma GEMM (U @ W') + tanh + j-reduction + node tail.
// One block per (b,i). U processed in four 64-row quarters (hi+lo in shared).
// ---------------------------------------------------------------------------
#define LDA 264
#define LDB 68
#define LDD 68

__global__ __launch_bounds__(256, 1) void k_spatial(
    const float* __restrict__ h,    const float* __restrict__ x,
    const float* __restrict__ v,
    const float* __restrict__ W_xmix,
    const float* __restrict__ W_p1, const float* __restrict__ b_p1,
    const float* __restrict__ W_p2, const float* __restrict__ b_p2,
    const float* __restrict__ W_n1, const float* __restrict__ b_n1,
    const float* __restrict__ W_n2, const float* __restrict__ b_n2,
    const float* __restrict__ W_v1, const float* __restrict__ b_v1,
    const float* __restrict__ W_v2, const float* __restrict__ W_vmix,
    float* __restrict__ out)
{
    extern __shared__ __align__(32) float sm[];
    float* sAhi  = sm;                 // 64*264 = 16896
    float* sAlo  = sAhi + 64*LDA;      // 16896
    float* sBhi  = sAlo + 64*LDA;      // 32*68 = 2176
    float* sBlo  = sBhi + 32*LDB;      // 2176
    float* sD    = sBlo + 32*LDB;      // 64*68 = 4352
    float* sXh   = sD + 64*LDD;        // 1024
    float* sComb = sXh + 1024;         // 768
    float* sHes  = sComb + 768;        // 256
    float* sPart = sHes + 256;         // 768
    float* sHi   = sPart + 768;        // 64
    float* sT1   = sHi + 64;           // 64
    float* sT2   = sT1 + 64;           // 64
    float* sHn   = sT2 + 64;           // 64
    float* sCn   = sHn + 64;           // 256
    float* sMisc = sCn + 256;          // 16

    const int t  = threadIdx.x;
    const int bi = blockIdx.x;
    const int b  = bi >> 8;
    const int i  = bi & 255;
    const int w  = t >> 5, lane = t & 31;
    const int wr = w & 3;     // M tile (16 rows)
    const int wn = w >> 1 & 2;// unused placeholder (recomputed below)
    const int wnn = w >> 2;   // N half (32 cols)

    sHes[t] = g_hes[bi*NC + t];
    if (t < 64) sHi[t] = h[(b*NN + i)*64 + t];
    {
        const int j = t;
        const float xi0 = x[(b*NN+i)*3+0], xi1 = x[(b*NN+i)*3+1], xi2 = x[(b*NN+i)*3+2];
        const float dx = x[(b*NN+j)*3+0]-xi0;
        const float dy = x[(b*NN+j)*3+1]-xi1;
        const float dz = x[(b*NN+j)*3+2]-xi2;
        const float ssq = dx*dx + dy*dy + dz*dz;
        const float dd  = sqrtf(fmaxf(ssq, 0.f) + 1e-5f);
        const float inv = 1.f/(dd + 1e-5f);
        sXh[j*4+0] = dx*inv; sXh[j*4+1] = dy*inv; sXh[j*4+2] = dz*inv;
    }
    __syncthreads();

    for (int qr = 0; qr < 4; qr++) {
        // stage A quarter: rows [qr*64, +64), all 256 c', hi/lo split
        {
            const float4* gu = (const float4*)(g_U + ((size_t)bi*NN + qr*64)*NC);
            #pragma unroll
            for (int it = 0; it < 16; it++) {
                const int l  = t + it*256;
                const int jr = l >> 6;
                const int f4 = l & 63;
                float4 uv = gu[jr*64 + f4];
                float4 uh, ul;
                uh.x = tf32r(uv.x); ul.x = tf32r(uv.x - uh.x);
                uh.y = tf32r(uv.y); ul.y = tf32r(uv.y - uh.y);
                uh.z = tf32r(uv.z); ul.z = tf32r(uv.z - uh.z);
                uh.w = tf32r(uv.w); ul.w = tf32r(uv.w - uh.w);
                *(float4*)(sAhi + jr*LDA + f4*4) = uh;
                *(float4*)(sAlo + jr*LDA + f4*4) = ul;
            }
        }
        __syncthreads();

        for (int q = 0; q < 4; q++) {
            wmma::fragment<wmma::accumulator,16,16,8,float> acc[2];
            #pragma unroll
            for (int ni = 0; ni < 2; ni++) wmma::fill_fragment(acc[ni], 0.f);

            for (int stage = 0; stage < 8; stage++) {
                // stage B: K rows [stage*32,+32) (row-permuted), cols [q*64,+64)
                #pragma unroll
                for (int it = 0; it < 2; it++) {
                    const int l  = t + it*256;
                    const int r  = l >> 4;
                    const int f4 = l & 15;
                    const int kk = stage*32 + r;
                    const int grow = ((kk & 63) << 2) + (kk >> 6);
                    float4 wv = *(const float4*)(W_xmix + grow*NC + q*64 + f4*4);
                    float4 wh, wl;
                    wh.x = tf32r(wv.x); wl.x = tf32r(wv.x - wh.x);
                    wh.y = tf32r(wv.y); wl.y = tf32r(wv.y - wh.y);
                    wh.z = tf32r(wv.z); wl.z = tf32r(wv.z - wh.z);
                    wh.w = tf32r(wv.w); wl.w = tf32r(wv.w - wh.w);
                    *(float4*)(sBhi + r*LDB + f4*4) = wh;
                    *(float4*)(sBlo + r*LDB + f4*4) = wl;
                }
                __syncthreads();

                #pragma unroll
                for (int ks = 0; ks < 4; ks++) {
                    wmma::fragment<wmma::matrix_a,16,16,8,wmma::precision::tf32,wmma::row_major> ah, al;
                    wmma::load_matrix_sync(ah, sAhi + (wr*16)*LDA + stage*32 + ks*8, LDA);
                    wmma::load_matrix_sync(al, sAlo + (wr*16)*LDA + stage*32 + ks*8, LDA);
                    #pragma unroll
                    for (int ni = 0; ni < 2; ni++) {
                        wmma::fragment<wmma::matrix_b,16,16,8,wmma::precision::tf32,wmma::row_major> bh, bl;
                        wmma::load_matrix_sync(bh, sBhi + (ks*8)*LDB + wnn*32 + ni*16, LDB);
                        wmma::load_matrix_sync(bl, sBlo + (ks*8)*LDB + wnn*32 + ni*16, LDB);
                        wmma::mma_sync(acc[ni], al, bh, acc[ni]);
                        wmma::mma_sync(acc[ni], ah, bl, acc[ni]);
                        wmma::mma_sync(acc[ni], ah, bh, acc[ni]);
                    }
                }
                __syncthreads();
            }

            // epilogue for this (qr, q): D -> tanh -> weighted j-reduction
            #pragma unroll
            for (int ni = 0; ni < 2; ni++)
                wmma::store_matrix_sync(sD + (wr*16)*LDD + wnn*32 + ni*16, acc[ni], LDD, wmma::mem_row_major);
            __syncthreads();
            {
                const int kq = t & 63, grp = t >> 6;     // 4 groups x 16 rows
                float p0 = 0.f, p1 = 0.f, p2 = 0.f;
                #pragma unroll
                for (int r = 0; r < 16; r++) {
                    const int jl = grp*16 + r;
                    const int jj = qr*64 + jl;
                    const float c = tanhap(sD[jl*LDD + kq]);
                    p0 += c * sXh[jj*4+0];
                    p1 += c * sXh[jj*4+1];
                    p2 += c * sXh[jj*4+2];
                }
                const int pb = ((grp<<6) + kq)*3;
                sPart[pb+0] = p0; sPart[pb+1] = p1; sPart[pb+2] = p2;
            }
            __syncthreads();
            if (t < 192) {
                const int kl = t/3, dd = t - kl*3;
                float s = sPart[(kl)*3+dd] + sPart[((1<<6)+kl)*3+dd]
                        + sPart[((2<<6)+kl)*3+dd] + sPart[((3<<6)+kl)*3+dd];
                s *= (1.f/NN);
                const int ci = (q*64 + kl)*3 + dd;
                if (qr == 0) sComb[ci] = s; else sComb[ci] += s;
            }
            __syncthreads();
        }
        __syncthreads();
    }

    // ---- node tail ----
    {
        const float c0 = sComb[t*3+0], c1 = sComb[t*3+1], c2 = sComb[t*3+2];
        sCn[t] = c0*c0 + c1*c1 + c2*c2;
    }
    __syncthreads();
    if (t < 64) {
        float a = b_p1[t];
        for (int c = 0; c < 256; c++) a += sCn[c]*W_p1[c*64 + t];
        sT1[t] = siluf(a);
    }
    __syncthreads();
    if (t < 64) {
        float a = b_p2[t];
        for (int c = 0; c < 64; c++) a += sT1[c]*W_p2[c*64 + t];
        sT2[t] = siluf(a);   // h_comb
    }
    __syncthreads();
    if (t < 64) {
        float a = b_n1[t];
        for (int r = 0; r < 64;  r++) a += sHi[r] *W_n1[r*64 + t];
        for (int r = 0; r < 256; r++) a += sHes[r]*W_n1[(64+r)*64 + t];
        for (int r = 0; r < 64;  r++) a += sT2[r] *W_n1[(320+r)*64 + t];
        sT1[t] = siluf(a);
    }
    __syncthreads();
    if (t < 64) {
        float a = b_n2[t];
        for (int c = 0; c < 64; c++) a += sT1[c]*W_n2[c*64 + t];
        const float hn = sHi[t] + siluf(a);
        sHn[t] = hn;
        out[(b*NN + i)*64 + t] = hn;
    }
    __syncthreads();
    if (t < 64) {
        float a = b_v1[t];
        for (int c = 0; c < 64; c++) a += sHn[c]*W_v1[c*64 + t];
        sT1[t] = siluf(a);
    }
    __syncthreads();
    if (w == 0) {            // v_scale
        float s = sT1[lane]*W_v2[lane] + sT1[lane+32]*W_v2[lane+32];
        #pragma unroll
        for (int o = 16; o; o >>= 1) s += __shfl_xor_sync(~0u, s, o);
        if (lane == 0) sMisc[0] = 2.f/(1.f + __expf(-s));
    }
    if (w >= 1 && w <= 3) {  // delta_v
        const int dd = w - 1;
        float s = 0.f;
        for (int q2 = 0; q2 < 8; q2++)
            s += sComb[(lane + 32*q2)*3 + dd]*W_vmix[lane + 32*q2];
        #pragma unroll
        for (int o = 16; o; o >>= 1) s += __shfl_xor_sync(~0u, s, o);
        if (lane == 0) sMisc[1+dd] = s;
    }
    __syncthreads();
    if (t < 3) {
        const float vn = sMisc[1+t] + sMisc[0]*v[(b*NN+i)*3 + t];
        const float xn = x[(b*NN+i)*3 + t] + vn;
        out[NB*NN*64 + (b*NN+i)*3 + t]           = xn;
        out[NB*NN*64 + NB*NN*3 + (b*NN+i)*3 + t] = vn;
    }
}

// ---------------------------------------------------------------------------
extern "C" void kernel_launch(void* const* d_in, const int* in_sizes, int n_in,
                              void* d_out, int out_size)
{
    const float* h      = (const float*)d_in[0];
    const float* x      = (const float*)d_in[1];
    const float* v      = (const float*)d_in[2];
    const float* W_in   = (const float*)d_in[3];
    const float* b_in   = (const float*)d_in[4];
    const float* means  = (const float*)d_in[5];
    const float* betas  = (const float*)d_in[6];
    const float* W_o1   = (const float*)d_in[7];
    const float* b_o1   = (const float*)d_in[8];
    const float* W_o2   = (const float*)d_in[9];
    const float* b_o2   = (const float*)d_in[10];
    const float* W_sem  = (const float*)d_in[11];
    const float* b_sem  = (const float*)d_in[12];
    const float* W_xmix = (const float*)d_in[13];
    const float* W_p1   = (const float*)d_in[14];
    const float* b_p1   = (const float*)d_in[15];
    const float* W_p2   = (const float*)d_in[16];
    const float* b_p2   = (const float*)d_in[17];
    const float* W_n1   = (const float*)d_in[18];
    const float* b_n1   = (const float*)d_in[19];
    const float* W_n2   = (const float*)d_in[20];
    const float* b_n2   = (const float*)d_in[21];
    const float* W_v1   = (const float*)d_in[22];
    const float* b_v1   = (const float*)d_in[23];
    const float* W_v2   = (const float*)d_in[24];
    const float* W_vmix = (const float*)d_in[25];
    float* out = (float*)d_out;

    const size_t smA = (size_t)(NN*65 + 128*NKF + DCAT*64 + 64*64 + 256
                                + 3*NKF + 2*64 + 8 + NN*3 + 4*NN + 16) * sizeof(float);
    const size_t smB = (size_t)(2*64*LDA + 2*32*LDB + 64*LDD + 1024 + 768 + 256
                                + 768 + 4*64 + 256 + 16) * sizeof(float);

    cudaFuncSetAttribute(k_edge,    cudaFuncAttributeMaxDynamicSharedMemorySize, (int)smA);
    cudaFuncSetAttribute(k_spatial, cudaFuncAttributeMaxDynamicSharedMemorySize, (int)smB);

    k_edge<<<NB*NN, 256, smA>>>(h, x, W_in, b_in, means, betas,
                                W_o1, b_o1, W_o2, b_o2, W_sem, b_sem);
    k_spatial<<<NB*NN, 256, smB>>>(h, x, v, W_xmix, W_p1, b_p1, W_p2, b_p2,
                                   W_n1, b_n1, W_n2, b_n2, W_v1, b_v1,
                                   W_v2, W_vmix, out);
}

// round 4
// speedup vs baseline: 1.5630x; 1.5630x over previous
#include <cuda_runtime.h>
#include <cuda_bf16.h>
#include <mma.h>
#include <math.h>

using namespace nvcuda;

#define NB   2
#define NN   256
#define NF   64
#define NKF  50
#define NH   4
#define NC   256
#define DCAT 179   // 2F + KF + 1

// scratch (static device memory; allocation-free)
__device__ __nv_bfloat16 g_Uhi[(size_t)NB*NN*NN*NC];  // [bi][j][c'] hi part (67MB)
__device__ __nv_bfloat16 g_Ulo[(size_t)NB*NN*NN*NC];  // lo part
__device__ __nv_bfloat16 g_Bhi[NC*NC];                // permuted W_xmix hi
__device__ __nv_bfloat16 g_Blo[NC*NC];                // permuted W_xmix lo
__device__ float g_hes[NB*NN*NC];                     // [bi][c] c=f*4+hd

__device__ __forceinline__ float siluf(float v){ return v / (1.f + __expf(-v)); }
__device__ __forceinline__ float tanhap(float x){
    float y; asm("tanh.approx.f32 %0, %1;" : "=f"(y) : "f"(x)); return y;
}
__device__ __forceinline__ void bf16split(float x, __nv_bfloat16& hi, __nv_bfloat16& lo){
    hi = __float2bfloat16(x);
    lo = __float2bfloat16(x - __bfloat162float(hi));
}

// ---------------------------------------------------------------------------
// Prep: split + row-permute W_xmix into bf16 hi/lo (K-row kk <- orig row
// (kk&63)*4 + (kk>>6), matching U's c' = hd*64+f ordering).
// ---------------------------------------------------------------------------
__global__ void k_prep(const float* __restrict__ W_xmix) {
    const int kk = blockIdx.x, c = threadIdx.x;
    const int grow = ((kk & 63) << 2) + (kk >> 6);
    __nv_bfloat16 hi, lo;
    bf16split(W_xmix[grow*NC + c], hi, lo);
    g_Bhi[kk*NC + c] = hi;
    g_Blo[kk*NC + c] = lo;
}

// ---------------------------------------------------------------------------
// Kernel A: edge MLP + semantic attention softmax. One block per (b,i),
// thread j handles pair (i,j). Emits g_Uhi/g_Ulo (bf16) and g_hes (fp32).
// ---------------------------------------------------------------------------
__global__ __launch_bounds__(256, 1) void k_edge(
    const float* __restrict__ h,     const float* __restrict__ x,
    const float* __restrict__ W_in,  const float* __restrict__ b_in,
    const float* __restrict__ means, const float* __restrict__ betas,
    const float* __restrict__ W_o1,  const float* __restrict__ b_o1,
    const float* __restrict__ W_o2,  const float* __restrict__ b_o2,
    const float* __restrict__ W_sem, const float* __restrict__ b_sem)
{
    extern __shared__ __align__(32) float sm[];
    float* sh_h  = sm;                 // 256*65
    float* sWin  = sh_h + NN*65;       // 6400
    float* sWo1  = sWin + 128*NKF;     // 11456
    float* sWo2  = sWo1 + DCAT*64;     // 4096
    float* sWsem = sWo2 + 64*64;       // 256
    float* sbin  = sWsem + 256;
    float* smean = sbin + NKF;
    float* sbeta = smean + NKF;
    float* sbo1  = sbeta + NKF;
    float* sbo2  = sbo1 + 64;
    float* sbsem = sbo2 + 64;
    float* sx    = sbsem + 8;
    float* sLog  = sx + NN*3;
    float* sRed  = sLog + 4*NN;
    // phase-2 aliases (weight region reused after sync)
    float* sHeMat = sWin;              // 256*65
    float* sAttS  = sWin + 16640;      // 256*4

    const int t  = threadIdx.x;
    const int bi = blockIdx.x;
    const int b  = bi >> 8;
    const int i  = bi & 255;

    for (int l = t; l < NN*NF;   l += 256) sh_h[(l>>6)*65 + (l&63)] = h[b*NN*NF + l];
    for (int l = t; l < 128*NKF; l += 256) sWin[l] = W_in[l];
    for (int l = t; l < DCAT*64; l += 256) sWo1[l] = W_o1[l];
    for (int l = t; l < 64*64;   l += 256) sWo2[l] = W_o2[l];
    sWsem[t] = W_sem[t];
    if (t < NKF) { sbin[t]=b_in[t]; smean[t]=means[t]; sbeta[t]=betas[t]; }
    if (t < 64)  { sbo1[t]=b_o1[t]; sbo2[t]=b_o2[t]; }
    if (t < 4)   sbsem[t]=b_sem[t];
    for (int l = t; l < NN*3; l += 256) sx[l] = x[b*NN*3 + l];
    __syncthreads();

    const int j = t;
    const float dx = sx[j*3+0]-sx[i*3+0];
    const float dy = sx[j*3+1]-sx[i*3+1];
    const float dz = sx[j*3+2]-sx[i*3+2];
    const float ss = dx*dx + dy*dy + dz*dz;
    const float d  = sqrtf(fmaxf(ss, 0.f) + 1e-5f);

    float h1[NKF];
    #pragma unroll
    for (int k = 0; k < NKF; k++) h1[k] = sbin[k];
    const float* hj = sh_h + j*65;
    const float* hi = sh_h + i*65;
    for (int f = 0; f < NF; f++) {
        const float vj = hj[f], vi = hi[f];
        const float2* rj = (const float2*)(sWin + f*NKF);
        const float2* ri = (const float2*)(sWin + (64+f)*NKF);
        #pragma unroll
        for (int k2 = 0; k2 < NKF/2; k2++) {
            float2 wj = rj[k2], wi = ri[k2];
            h1[2*k2]   += vj*wj.x + vi*wi.x;
            h1[2*k2+1] += vj*wj.y + vi*wi.y;
        }
    }

    const float em  = __expf(-d);
    const float cut = (d < 5.f) ? 0.5f*(__cosf(d*0.6283185307179586f)+1.f) : 0.f;
    float rh[NKF];
    #pragma unroll
    for (int k = 0; k < NKF; k++) {
        float dm = em - smean[k];
        rh[k] = cut * __expf(-sbeta[k]*dm*dm) * h1[k];
    }

    float tv[64];
    #pragma unroll
    for (int k = 0; k < 64; k++) tv[k] = sbo1[k];
    auto acc_row = [&](float val, const float* row) {
        const float4* r4 = (const float4*)row;
        #pragma unroll
        for (int q = 0; q < 16; q++) {
            float4 w = r4[q];
            tv[4*q+0] += val*w.x; tv[4*q+1] += val*w.y;
            tv[4*q+2] += val*w.z; tv[4*q+3] += val*w.w;
        }
    };
    for (int f = 0; f < 64; f++) acc_row(hj[f], sWo1 + f*64);
    for (int f = 0; f < 64; f++) acc_row(hi[f], sWo1 + (64+f)*64);
    #pragma unroll
    for (int k = 0; k < NKF; k++) acc_row(rh[k], sWo1 + (128+k)*64);
    acc_row(d, sWo1 + 178*64);
    #pragma unroll
    for (int k = 0; k < 64; k++) tv[k] = siluf(tv[k]);

    float he[64];
    #pragma unroll
    for (int k = 0; k < 64; k++) he[k] = sbo2[k];
    #pragma unroll
    for (int c = 0; c < 64; c++) {
        const float val = tv[c];
        const float4* r4 = (const float4*)(sWo2 + c*64);
        #pragma unroll
        for (int q = 0; q < 16; q++) {
            float4 w = r4[q];
            he[4*q+0] += val*w.x; he[4*q+1] += val*w.y;
            he[4*q+2] += val*w.z; he[4*q+3] += val*w.w;
        }
    }

    float l0=sbsem[0], l1=sbsem[1], l2=sbsem[2], l3=sbsem[3];
    #pragma unroll
    for (int f = 0; f < 64; f++) {
        const float v4 = he[f];
        l0 += v4*sWsem[f*4+0]; l1 += v4*sWsem[f*4+1];
        l2 += v4*sWsem[f*4+2]; l3 += v4*sWsem[f*4+3];
    }
    float lg[4] = {l0, l1, l2, l3};
    #pragma unroll
    for (int hd = 0; hd < 4; hd++) {
        float a = lg[hd];
        a = (a > 0.f) ? a : 2.f*(__expf(0.5f*a) - 1.f);
        if (j == i) a -= 1e5f;
        lg[hd] = a;
    }

    __syncthreads();
    #pragma unroll
    for (int f = 0; f < 64; f++) sHeMat[j*65 + f] = he[f];
    #pragma unroll
    for (int hd = 0; hd < 4; hd++) sLog[hd*NN + j] = lg[hd];
    __syncthreads();

    const int wp = t >> 5, lane = t & 31;
    if (wp < 4) {
        float m = -1e30f;
        for (int q = 0; q < 8; q++) m = fmaxf(m, sLog[wp*NN + lane + 32*q]);
        #pragma unroll
        for (int o = 16; o; o >>= 1) m = fmaxf(m, __shfl_xor_sync(~0u, m, o));
        float s = 0.f;
        for (int q = 0; q < 8; q++) s += __expf(sLog[wp*NN + lane + 32*q] - m);
        #pragma unroll
        for (int o = 16; o; o >>= 1) s += __shfl_xor_sync(~0u, s, o);
        if (lane == 0) { sRed[wp*2] = m; sRed[wp*2+1] = s; }
    }
    __syncthreads();

    float att4[4];
    #pragma unroll
    for (int hd = 0; hd < 4; hd++) {
        att4[hd] = __expf(sLog[hd*NN + j] - sRed[hd*2]) / sRed[hd*2+1];
        sAttS[j*4 + hd] = att4[hd];
    }
    // write U row (c' = hd*64 + f) as bf16 hi/lo
    {
        __nv_bfloat162* uh = (__nv_bfloat162*)(g_Uhi + ((size_t)bi*NN + j)*NC);
        __nv_bfloat162* ul = (__nv_bfloat162*)(g_Ulo + ((size_t)bi*NN + j)*NC);
        #pragma unroll
        for (int c2 = 0; c2 < 128; c2++) {
            const int i0 = 2*c2;
            const float u0 = att4[(i0+0)>>6] * he[(i0+0)&63];
            const float u1 = att4[(i0+1)>>6] * he[(i0+1)&63];
            __nv_bfloat16 h0, l0b, h1b, l1b;
            bf16split(u0, h0, l0b);
            bf16split(u1, h1b, l1b);
            uh[c2] = __nv_bfloat162(h0, h1b);
            ul[c2] = __nv_bfloat162(l0b, l1b);
        }
    }
    __syncthreads();

    {
        const int f = t >> 2, hd = t & 3;
        float s = 0.f;
        for (int jj = 0; jj < NN; jj++) s += sHeMat[jj*65 + f] * sAttS[jj*4 + hd];
        g_hes[bi*NC + t] = s;
    }
}

// ---------------------------------------------------------------------------
// Kernel B: bf16x2-split wmma GEMM (U @ W') + tanh + j-reduction + node tail.
// A: 64-row quarters resident; B: full-K 64-col panels resident.
// ---------------------------------------------------------------------------
#define LDA 264   // bf16 elems (multiple of 8)
#define LDB 72    // bf16 elems
#define LDD 68    // floats

__global__ __launch_bounds__(256, 1) void k_spatial(
    const float* __restrict__ h,    const float* __restrict__ x,
    const float* __restrict__ v,
    const float* __restrict__ W_p1, const float* __restrict__ b_p1,
    const float* __restrict__ W_p2, const float* __restrict__ b_p2,
    const float* __restrict__ W_n1, const float* __restrict__ b_n1,
    const float* __restrict__ W_n2, const float* __restrict__ b_n2,
    const float* __restrict__ W_v1, const float* __restrict__ b_v1,
    const float* __restrict__ W_v2, const float* __restrict__ W_vmix,
    float* __restrict__ out)
{
    extern __shared__ __align__(16) char smraw[];
    __nv_bfloat16* sAhi = (__nv_bfloat16*)smraw;        // 64*264
    __nv_bfloat16* sAlo = sAhi + 64*LDA;
    __nv_bfloat16* sBhi = sAlo + 64*LDA;                // 256*72
    __nv_bfloat16* sBlo = sBhi + 256*LDB;
    float* sD    = (float*)(sBlo + 256*LDB);            // 64*68
    float* sXh   = sD + 64*LDD;        // 1024
    float* sComb = sXh + 1024;         // 768
    float* sHes  = sComb + 768;        // 256
    float* sPart = sHes + 256;         // 768
    float* sHi   = sPart + 768;        // 64
    float* sT1   = sHi + 64;           // 64
    float* sT2   = sT1 + 64;           // 64
    float* sHn   = sT2 + 64;           // 64
    float* sCn   = sHn + 64;           // 256
    float* sMisc = sCn + 256;          // 16

    const int t  = threadIdx.x;
    const int bi = blockIdx.x;
    const int b  = bi >> 8;
    const int i  = bi & 255;
    const int w  = t >> 5, lane = t & 31;
    const int wr = w & 3;     // M tile (16 rows)
    const int wn = w >> 2;    // N half (32 cols)

    sHes[t] = g_hes[bi*NC + t];
    if (t < 64) sHi[t] = h[(b*NN + i)*64 + t];
    {
        const int j = t;
        const float xi0 = x[(b*NN+i)*3+0], xi1 = x[(b*NN+i)*3+1], xi2 = x[(b*NN+i)*3+2];
        const float dx = x[(b*NN+j)*3+0]-xi0;
        const float dy = x[(b*NN+j)*3+1]-xi1;
        const float dz = x[(b*NN+j)*3+2]-xi2;
        const float ssq = dx*dx + dy*dy + dz*dz;
        const float dd  = sqrtf(fmaxf(ssq, 0.f) + 1e-5f);
        const float inv = 1.f/(dd + 1e-5f);
        sXh[j*4+0] = dx*inv; sXh[j*4+1] = dy*inv; sXh[j*4+2] = dz*inv;
    }
    __syncthreads();

    for (int qr = 0; qr < 4; qr++) {
        // stage A quarter (64 rows x 256 K) hi/lo: pure 16B copies
        {
            const uint4* ghi = (const uint4*)(g_Uhi + ((size_t)bi*NN + qr*64)*NC);
            const uint4* glo = (const uint4*)(g_Ulo + ((size_t)bi*NN + qr*64)*NC);
            #pragma unroll
            for (int it = 0; it < 8; it++) {
                const int l  = t + it*256;
                const int jr = l >> 5;     // row 0..63
                const int f8 = l & 31;     // 8-bf16 chunk 0..31
                *(uint4*)(sAhi + jr*LDA + f8*8) = ghi[jr*32 + f8];
                *(uint4*)(sAlo + jr*LDA + f8*8) = glo[jr*32 + f8];
            }
        }
        __syncthreads();

        for (int q = 0; q < 4; q++) {
            // stage B panel (256 K x 64 cols) hi/lo
            {
                const uint4* gbh = (const uint4*)g_Bhi;
                const uint4* gbl = (const uint4*)g_Blo;
                #pragma unroll
                for (int it = 0; it < 8; it++) {
                    const int l  = t + it*256;
                    const int kk = l >> 3;     // K row 0..255
                    const int f8 = l & 7;      // chunk 0..7
                    *(uint4*)(sBhi + kk*LDB + f8*8) = gbh[kk*32 + q*8 + f8];
                    *(uint4*)(sBlo + kk*LDB + f8*8) = gbl[kk*32 + q*8 + f8];
                }
            }
            __syncthreads();

            wmma::fragment<wmma::accumulator,16,16,16,float> acc[2];
            #pragma unroll
            for (int ni = 0; ni < 2; ni++) wmma::fill_fragment(acc[ni], 0.f);

            #pragma unroll 4
            for (int ks = 0; ks < 16; ks++) {
                wmma::fragment<wmma::matrix_a,16,16,16,__nv_bfloat16,wmma::row_major> ah, al;
                wmma::load_matrix_sync(ah, sAhi + (wr*16)*LDA + ks*16, LDA);
                wmma::load_matrix_sync(al, sAlo + (wr*16)*LDA + ks*16, LDA);
                #pragma unroll
                for (int ni = 0; ni < 2; ni++) {
                    wmma::fragment<wmma::matrix_b,16,16,16,__nv_bfloat16,wmma::row_major> bh, bl;
                    wmma::load_matrix_sync(bh, sBhi + (ks*16)*LDB + wn*32 + ni*16, LDB);
                    wmma::load_matrix_sync(bl, sBlo + (ks*16)*LDB + wn*32 + ni*16, LDB);
                    wmma::mma_sync(acc[ni], ah, bh, acc[ni]);
                    wmma::mma_sync(acc[ni], ah, bl, acc[ni]);
                    wmma::mma_sync(acc[ni], al, bh, acc[ni]);
                }
            }
            __syncthreads();   // sD free (previous epilogue done)

            #pragma unroll
            for (int ni = 0; ni < 2; ni++)
                wmma::store_matrix_sync(sD + (wr*16)*LDD + wn*32 + ni*16, acc[ni], LDD, wmma::mem_row_major);
            __syncthreads();

            {   // tanh + xhat-weighted partial reduction (4 groups x 16 rows)
                const int kq = t & 63, grp = t >> 6;
                float p0 = 0.f, p1 = 0.f, p2 = 0.f;
                #pragma unroll
                for (int r = 0; r < 16; r++) {
                    const int jl = grp*16 + r;
                    const int jj = qr*64 + jl;
                    const float c = tanhap(sD[jl*LDD + kq]);
                    p0 += c * sXh[jj*4+0];
                    p1 += c * sXh[jj*4+1];
                    p2 += c * sXh[jj*4+2];
                }
                const int pb = ((grp<<6) + kq)*3;
                sPart[pb+0] = p0; sPart[pb+1] = p1; sPart[pb+2] = p2;
            }
            __syncthreads();
            if (t < 192) {
                const int kl = t/3, dd = t - kl*3;
                float s = sPart[kl*3+dd] + sPart[(64+kl)*3+dd]
                        + sPart[(128+kl)*3+dd] + sPart[(192+kl)*3+dd];
                s *= (1.f/NN);
                const int ci = (q*64 + kl)*3 + dd;
                if (qr == 0) sComb[ci] = s; else sComb[ci] += s;
            }
            __syncthreads();
        }
    }

    // ---- node tail ----
    {
        const float c0 = sComb[t*3+0], c1 = sComb[t*3+1], c2 = sComb[t*3+2];
        sCn[t] = c0*c0 + c1*c1 + c2*c2;
    }
    __syncthreads();
    if (t < 64) {
        float a = b_p1[t];
        for (int c = 0; c < 256; c++) a += sCn[c]*W_p1[c*64 + t];
        sT1[t] = siluf(a);
    }
    __syncthreads();
    if (t < 64) {
        float a = b_p2[t];
        for (int c = 0; c < 64; c++) a += sT1[c]*W_p2[c*64 + t];
        sT2[t] = siluf(a);
    }
    __syncthreads();
    if (t < 64) {
        float a = b_n1[t];
        for (int r = 0; r < 64;  r++) a += sHi[r] *W_n1[r*64 + t];
        for (int r = 0; r < 256; r++) a += sHes[r]*W_n1[(64+r)*64 + t];
        for (int r = 0; r < 64;  r++) a += sT2[r] *W_n1[(320+r)*64 + t];
        sT1[t] = siluf(a);
    }
    __syncthreads();
    if (t < 64) {
        float a = b_n2[t];
        for (int c = 0; c < 64; c++) a += sT1[c]*W_n2[c*64 + t];
        const float hn = sHi[t] + siluf(a);
        sHn[t] = hn;
        out[(b*NN + i)*64 + t] = hn;
    }
    __syncthreads();
    if (t < 64) {
        float a = b_v1[t];
        for (int c = 0; c < 64; c++) a += sHn[c]*W_v1[c*64 + t];
        sT1[t] = siluf(a);
    }
    __syncthreads();
    if (w == 0) {
        float s = sT1[lane]*W_v2[lane] + sT1[lane+32]*W_v2[lane+32];
        #pragma unroll
        for (int o = 16; o; o >>= 1) s += __shfl_xor_sync(~0u, s, o);
        if (lane == 0) sMisc[0] = 2.f/(1.f + __expf(-s));
    }
    if (w >= 1 && w <= 3) {
        const int dd = w - 1;
        float s = 0.f;
        for (int q2 = 0; q2 < 8; q2++)
            s += sComb[(lane + 32*q2)*3 + dd]*W_vmix[lane + 32*q2];
        #pragma unroll
        for (int o = 16; o; o >>= 1) s += __shfl_xor_sync(~0u, s, o);
        if (lane == 0) sMisc[1+dd] = s;
    }
    __syncthreads();
    if (t < 3) {
        const float vn = sMisc[1+t] + sMisc[0]*v[(b*NN+i)*3 + t];
        const float xn = x[(b*NN+i)*3 + t] + vn;
        out[NB*NN*64 + (b*NN+i)*3 + t]           = xn;
        out[NB*NN*64 + NB*NN*3 + (b*NN+i)*3 + t] = vn;
    }
}

// ---------------------------------------------------------------------------
extern "C" void kernel_launch(void* const* d_in, const int* in_sizes, int n_in,
                              void* d_out, int out_size)
{
    const float* h      = (const float*)d_in[0];
    const float* x      = (const float*)d_in[1];
    const float* v      = (const float*)d_in[2];
    const float* W_in   = (const float*)d_in[3];
    const float* b_in   = (const float*)d_in[4];
    const float* means  = (const float*)d_in[5];
    const float* betas  = (const float*)d_in[6];
    const float* W_o1   = (const float*)d_in[7];
    const float* b_o1   = (const float*)d_in[8];
    const float* W_o2   = (const float*)d_in[9];
    const float* b_o2   = (const float*)d_in[10];
    const float* W_sem  = (const float*)d_in[11];
    const float* b_sem  = (const float*)d_in[12];
    const float* W_xmix = (const float*)d_in[13];
    const float* W_p1   = (const float*)d_in[14];
    const float* b_p1   = (const float*)d_in[15];
    const float* W_p2   = (const float*)d_in[16];
    const float* b_p2   = (const float*)d_in[17];
    const float* W_n1   = (const float*)d_in[18];
    const float* b_n1   = (const float*)d_in[19];
    const float* W_n2   = (const float*)d_in[20];
    const float* b_n2   = (const float*)d_in[21];
    const float* W_v1   = (const float*)d_in[22];
    const float* b_v1   = (const float*)d_in[23];
    const float* W_v2   = (const float*)d_in[24];
    const float* W_vmix = (const float*)d_in[25];
    float* out = (float*)d_out;

    const size_t smA = (size_t)(NN*65 + 128*NKF + DCAT*64 + 64*64 + 256
                                + 3*NKF + 2*64 + 8 + NN*3 + 4*NN + 16) * sizeof(float);
    const size_t smB = (size_t)(2*64*LDA + 2*256*LDB) * sizeof(__nv_bfloat16)
                     + (size_t)(64*LDD + 1024 + 768 + 256 + 768 + 4*64 + 256 + 16) * sizeof(float);

    cudaFuncSetAttribute(k_edge,    cudaFuncAttributeMaxDynamicSharedMemorySize, (int)smA);
    cudaFuncSetAttribute(k_spatial, cudaFuncAttributeMaxDynamicSharedMemorySize, (int)smB);

    k_prep<<<NC, NC>>>(W_xmix);
    k_edge<<<NB*NN, 256, smA>>>(h, x, W_in, b_in, means, betas,
                                W_o1, b_o1, W_o2, b_o2, W_sem, b_sem);
    k_spatial<<<NB*NN, 256, smB>>>(h, x, v, W_p1, b_p1, W_p2, b_p2,
                                   W_n1, b_n1, W_n2, b_n2, W_v1, b_v1,
                                   W_v2, W_vmix, out);
}

// round 6
// speedup vs baseline: 1.5668x; 1.0024x over previous
#include <cuda_runtime.h>
#include <cuda_bf16.h>
#include <mma.h>
#include <math.h>

using namespace nvcuda;

#define NB   2
#define NN   256
#define NF   64
#define NKF  50
#define NH   4
#define NC   256
#define DCAT 179   // 2F + KF + 1

// scratch (static device memory; allocation-free)
__device__ __nv_bfloat16 g_Uhi[(size_t)NB*NN*NN*NC];  // [bi][j][c'] hi part (67MB)
__device__ __nv_bfloat16 g_Ulo[(size_t)NB*NN*NN*NC];  // lo part
__device__ __nv_bfloat16 g_Bhi[NC*NC];                // permuted W_xmix hi
__device__ __nv_bfloat16 g_Blo[NC*NC];                // permuted W_xmix lo
__device__ float g_hes[NB*NN*NC];                     // [bi][c] c=f*4+hd

__device__ __forceinline__ float siluf(float v){ return v / (1.f + __expf(-v)); }
__device__ __forceinline__ float tanhap(float x){
    float y; asm("tanh.approx.f32 %0, %1;" : "=f"(y) : "f"(x)); return y;
}
__device__ __forceinline__ void bf16split(float x, __nv_bfloat16& hi, __nv_bfloat16& lo){
    hi = __float2bfloat16(x);
    lo = __float2bfloat16(x - __bfloat162float(hi));
}

// ---------------------------------------------------------------------------
// Prep: split + row-permute W_xmix into bf16 hi/lo (K-row kk <- orig row
// (kk&63)*4 + (kk>>6), matching U's c' = hd*64+f ordering).
// ---------------------------------------------------------------------------
__global__ void k_prep(const float* __restrict__ W_xmix) {
    const int kk = blockIdx.x, c = threadIdx.x;
    const int grow = ((kk & 63) << 2) + (kk >> 6);
    __nv_bfloat16 hi, lo;
    bf16split(W_xmix[grow*NC + c], hi, lo);
    g_Bhi[kk*NC + c] = hi;
    g_Blo[kk*NC + c] = lo;
}

// ---------------------------------------------------------------------------
// Kernel A: edge MLP + semantic attention softmax. One block per (b,i),
// thread j handles pair (i,j). Emits g_Uhi/g_Ulo (bf16) and g_hes (fp32).
// ---------------------------------------------------------------------------
__global__ __launch_bounds__(256, 1) void k_edge(
    const float* __restrict__ h,     const float* __restrict__ x,
    const float* __restrict__ W_in,  const float* __restrict__ b_in,
    const float* __restrict__ means, const float* __restrict__ betas,
    const float* __restrict__ W_o1,  const float* __restrict__ b_o1,
    const float* __restrict__ W_o2,  const float* __restrict__ b_o2,
    const float* __restrict__ W_sem, const float* __restrict__ b_sem)
{
    extern __shared__ __align__(32) float sm[];
    float* sh_h  = sm;                 // 256*65
    float* sWin  = sh_h + NN*65;       // 6400
    float* sWo1  = sWin + 128*NKF;     // 11456
    float* sWo2  = sWo1 + DCAT*64;     // 4096
    float* sWsem = sWo2 + 64*64;       // 256
    float* sbin  = sWsem + 256;
    float* smean = sbin + NKF;
    float* sbeta = smean + NKF;
    float* sbo1  = sbeta + NKF;
    float* sbo2  = sbo1 + 64;
    float* sbsem = sbo2 + 64;
    float* sx    = sbsem + 8;
    float* sLog  = sx + NN*3;
    float* sRed  = sLog + 4*NN;
    // phase-2 aliases (weight region reused after sync)
    float* sHeMat = sWin;              // 256*65
    float* sAttS  = sWin + 16640;      // 256*4

    const int t  = threadIdx.x;
    const int bi = blockIdx.x;
    const int b  = bi >> 8;
    const int i  = bi & 255;

    for (int l = t; l < NN*NF;   l += 256) sh_h[(l>>6)*65 + (l&63)] = h[b*NN*NF + l];
    for (int l = t; l < 128*NKF; l += 256) sWin[l] = W_in[l];
    for (int l = t; l < DCAT*64; l += 256) sWo1[l] = W_o1[l];
    for (int l = t; l < 64*64;   l += 256) sWo2[l] = W_o2[l];
    sWsem[t] = W_sem[t];
    if (t < NKF) { sbin[t]=b_in[t]; smean[t]=means[t]; sbeta[t]=betas[t]; }
    if (t < 64)  { sbo1[t]=b_o1[t]; sbo2[t]=b_o2[t]; }
    if (t < 4)   sbsem[t]=b_sem[t];
    for (int l = t; l < NN*3; l += 256) sx[l] = x[b*NN*3 + l];
    __syncthreads();

    const int j = t;
    const float dx = sx[j*3+0]-sx[i*3+0];
    const float dy = sx[j*3+1]-sx[i*3+1];
    const float dz = sx[j*3+2]-sx[i*3+2];
    const float ss = dx*dx + dy*dy + dz*dz;
    const float d  = sqrtf(fmaxf(ss, 0.f) + 1e-5f);

    float h1[NKF];
    #pragma unroll
    for (int k = 0; k < NKF; k++) h1[k] = sbin[k];
    const float* hj = sh_h + j*65;
    const float* hi = sh_h + i*65;
    for (int f = 0; f < NF; f++) {
        const float vj = hj[f], vi = hi[f];
        const float2* rj = (const float2*)(sWin + f*NKF);
        const float2* ri = (const float2*)(sWin + (64+f)*NKF);
        #pragma unroll
        for (int k2 = 0; k2 < NKF/2; k2++) {
            float2 wj = rj[k2], wi = ri[k2];
            h1[2*k2]   += vj*wj.x + vi*wi.x;
            h1[2*k2+1] += vj*wj.y + vi*wi.y;
        }
    }

    const float em  = __expf(-d);
    const float cut = (d < 5.f) ? 0.5f*(__cosf(d*0.6283185307179586f)+1.f) : 0.f;
    float rh[NKF];
    #pragma unroll
    for (int k = 0; k < NKF; k++) {
        float dm = em - smean[k];
        rh[k] = cut * __expf(-sbeta[k]*dm*dm) * h1[k];
    }

    float tv[64];
    #pragma unroll
    for (int k = 0; k < 64; k++) tv[k] = sbo1[k];
    auto acc_row = [&](float val, const float* row) {
        const float4* r4 = (const float4*)row;
        #pragma unroll
        for (int q = 0; q < 16; q++) {
            float4 w = r4[q];
            tv[4*q+0] += val*w.x; tv[4*q+1] += val*w.y;
            tv[4*q+2] += val*w.z; tv[4*q+3] += val*w.w;
        }
    };
    for (int f = 0; f < 64; f++) acc_row(hj[f], sWo1 + f*64);
    for (int f = 0; f < 64; f++) acc_row(hi[f], sWo1 + (64+f)*64);
    #pragma unroll
    for (int k = 0; k < NKF; k++) acc_row(rh[k], sWo1 + (128+k)*64);
    acc_row(d, sWo1 + 178*64);
    #pragma unroll
    for (int k = 0; k < 64; k++) tv[k] = siluf(tv[k]);

    float he[64];
    #pragma unroll
    for (int k = 0; k < 64; k++) he[k] = sbo2[k];
    #pragma unroll
    for (int c = 0; c < 64; c++) {
        const float val = tv[c];
        const float4* r4 = (const float4*)(sWo2 + c*64);
        #pragma unroll
        for (int q = 0; q < 16; q++) {
            float4 w = r4[q];
            he[4*q+0] += val*w.x; he[4*q+1] += val*w.y;
            he[4*q+2] += val*w.z; he[4*q+3] += val*w.w;
        }
    }

    float l0=sbsem[0], l1=sbsem[1], l2=sbsem[2], l3=sbsem[3];
    #pragma unroll
    for (int f = 0; f < 64; f++) {
        const float v4 = he[f];
        l0 += v4*sWsem[f*4+0]; l1 += v4*sWsem[f*4+1];
        l2 += v4*sWsem[f*4+2]; l3 += v4*sWsem[f*4+3];
    }
    float lg[4] = {l0, l1, l2, l3};
    #pragma unroll
    for (int hd = 0; hd < 4; hd++) {
        float a = lg[hd];
        a = (a > 0.f) ? a : 2.f*(__expf(0.5f*a) - 1.f);
        if (j == i) a -= 1e5f;
        lg[hd] = a;
    }

    __syncthreads();
    #pragma unroll
    for (int f = 0; f < 64; f++) sHeMat[j*65 + f] = he[f];
    #pragma unroll
    for (int hd = 0; hd < 4; hd++) sLog[hd*NN + j] = lg[hd];
    __syncthreads();

    const int wp = t >> 5, lane = t & 31;
    if (wp < 4) {
        float m = -1e30f;
        for (int q = 0; q < 8; q++) m = fmaxf(m, sLog[wp*NN + lane + 32*q]);
        #pragma unroll
        for (int o = 16; o; o >>= 1) m = fmaxf(m, __shfl_xor_sync(~0u, m, o));
        float s = 0.f;
        for (int q = 0; q < 8; q++) s += __expf(sLog[wp*NN + lane + 32*q] - m);
        #pragma unroll
        for (int o = 16; o; o >>= 1) s += __shfl_xor_sync(~0u, s, o);
        if (lane == 0) { sRed[wp*2] = m; sRed[wp*2+1] = s; }
    }
    __syncthreads();

    float att4[4];
    #pragma unroll
    for (int hd = 0; hd < 4; hd++) {
        att4[hd] = __expf(sLog[hd*NN + j] - sRed[hd*2]) / sRed[hd*2+1];
        sAttS[j*4 + hd] = att4[hd];
    }
    // write U row (c' = hd*64 + f) as bf16 hi/lo
    {
        __nv_bfloat162* uh = (__nv_bfloat162*)(g_Uhi + ((size_t)bi*NN + j)*NC);
        __nv_bfloat162* ul = (__nv_bfloat162*)(g_Ulo + ((size_t)bi*NN + j)*NC);
        #pragma unroll
        for (int c2 = 0; c2 < 128; c2++) {
            const int i0 = 2*c2;
            const float u0 = att4[(i0+0)>>6] * he[(i0+0)&63];
            const float u1 = att4[(i0+1)>>6] * he[(i0+1)&63];
            __nv_bfloat16 h0, l0b, h1b, l1b;
            bf16split(u0, h0, l0b);
            bf16split(u1, h1b, l1b);
            uh[c2] = __nv_bfloat162(h0, h1b);
            ul[c2] = __nv_bfloat162(l0b, l1b);
        }
    }
    __syncthreads();

    {
        const int f = t >> 2, hd = t & 3;
        float s = 0.f;
        for (int jj = 0; jj < NN; jj++) s += sHeMat[jj*65 + f] * sAttS[jj*4 + hd];
        g_hes[bi*NC + t] = s;
    }
}

// ---------------------------------------------------------------------------
// Kernel B: bf16x2-split wmma GEMM (U @ W') + tanh + j-reduction + node tail.
// A: 64-row quarters resident; B: full-K 64-col panels resident.
// ---------------------------------------------------------------------------
#define LDA 264   // bf16 elems (multiple of 8)
#define LDB 72    // bf16 elems
#define LDD 68    // floats

__global__ __launch_bounds__(256, 1) void k_spatial(
    const float* __restrict__ h,    const float* __restrict__ x,
    const float* __restrict__ v,
    const float* __restrict__ W_p1, const float* __restrict__ b_p1,
    const float* __restrict__ W_p2, const float* __restrict__ b_p2,
    const float* __restrict__ W_n1, const float* __restrict__ b_n1,
    const float* __restrict__ W_n2, const float* __restrict__ b_n2,
    const float* __restrict__ W_v1, const float* __restrict__ b_v1,
    const float* __restrict__ W_v2, const float* __restrict__ W_vmix,
    float* __restrict__ out)
{
    extern __shared__ __align__(16) char smraw[];
    __nv_bfloat16* sAhi = (__nv_bfloat16*)smraw;        // 64*264
    __nv_bfloat16* sAlo = sAhi + 64*LDA;
    __nv_bfloat16* sBhi = sAlo + 64*LDA;                // 256*72
    __nv_bfloat16* sBlo = sBhi + 256*LDB;
    float* sD    = (float*)(sBlo + 256*LDB);            // 64*68
    float* sXh   = sD + 64*LDD;        // 1024
    float* sComb = sXh + 1024;         // 768
    float* sHes  = sComb + 768;        // 256
    float* sPart = sHes + 256;         // 768
    float* sHi   = sPart + 768;        // 64
    float* sT1   = sHi + 64;           // 64
    float* sT2   = sT1 + 64;           // 64
    float* sHn   = sT2 + 64;           // 64
    float* sCn   = sHn + 64;           // 256
    float* sMisc = sCn + 256;          // 16

    const int t  = threadIdx.x;
    const int bi = blockIdx.x;
    const int b  = bi >> 8;
    const int i  = bi & 255;
    const int w  = t >> 5, lane = t & 31;
    const int wr = w & 3;     // M tile (16 rows)
    const int wn = w >> 2;    // N half (32 cols)

    sHes[t] = g_hes[bi*NC + t];
    if (t < 64) sHi[t] = h[(b*NN + i)*64 + t];
    {
        const int j = t;
        const float xi0 = x[(b*NN+i)*3+0], xi1 = x[(b*NN+i)*3+1], xi2 = x[(b*NN+i)*3+2];
        const float dx = x[(b*NN+j)*3+0]-xi0;
        const float dy = x[(b*NN+j)*3+1]-xi1;
        const float dz = x[(b*NN+j)*3+2]-xi2;
        const float ssq = dx*dx + dy*dy + dz*dz;
        const float dd  = sqrtf(fmaxf(ssq, 0.f) + 1e-5f);
        const float inv = 1.f/(dd + 1e-5f);
        sXh[j*4+0] = dx*inv; sXh[j*4+1] = dy*inv; sXh[j*4+2] = dz*inv;
    }
    __syncthreads();

    for (int qr = 0; qr < 4; qr++) {
        // stage A quarter (64 rows x 256 K) hi/lo: pure 16B copies
        {
            const uint4* ghi = (const uint4*)(g_Uhi + ((size_t)bi*NN + qr*64)*NC);
            const uint4* glo = (const uint4*)(g_Ulo + ((size_t)bi*NN + qr*64)*NC);
            #pragma unroll
            for (int it = 0; it < 8; it++) {
                const int l  = t + it*256;
                const int jr = l >> 5;     // row 0..63
                const int f8 = l & 31;     // 8-bf16 chunk 0..31
                *(uint4*)(sAhi + jr*LDA + f8*8) = ghi[jr*32 + f8];
                *(uint4*)(sAlo + jr*LDA + f8*8) = glo[jr*32 + f8];
            }
        }
        __syncthreads();

        for (int q = 0; q < 4; q++) {
            // stage B panel (256 K x 64 cols) hi/lo
            {
                const uint4* gbh = (const uint4*)g_Bhi;
                const uint4* gbl = (const uint4*)g_Blo;
                #pragma unroll
                for (int it = 0; it < 8; it++) {
                    const int l  = t + it*256;
                    const int kk = l >> 3;     // K row 0..255
                    const int f8 = l & 7;      // chunk 0..7
                    *(uint4*)(sBhi + kk*LDB + f8*8) = gbh[kk*32 + q*8 + f8];
                    *(uint4*)(sBlo + kk*LDB + f8*8) = gbl[kk*32 + q*8 + f8];
                }
            }
            __syncthreads();

            wmma::fragment<wmma::accumulator,16,16,16,float> acc[2];
            #pragma unroll
            for (int ni = 0; ni < 2; ni++) wmma::fill_fragment(acc[ni], 0.f);

            #pragma unroll 4
            for (int ks = 0; ks < 16; ks++) {
                wmma::fragment<wmma::matrix_a,16,16,16,__nv_bfloat16,wmma::row_major> ah, al;
                wmma::load_matrix_sync(ah, sAhi + (wr*16)*LDA + ks*16, LDA);
                wmma::load_matrix_sync(al, sAlo + (wr*16)*LDA + ks*16, LDA);
                #pragma unroll
                for (int ni = 0; ni < 2; ni++) {
                    wmma::fragment<wmma::matrix_b,16,16,16,__nv_bfloat16,wmma::row_major> bh, bl;
                    wmma::load_matrix_sync(bh, sBhi + (ks*16)*LDB + wn*32 + ni*16, LDB);
                    wmma::load_matrix_sync(bl, sBlo + (ks*16)*LDB + wn*32 + ni*16, LDB);
                    wmma::mma_sync(acc[ni], ah, bh, acc[ni]);
                    wmma::mma_sync(acc[ni], ah, bl, acc[ni]);
                    wmma::mma_sync(acc[ni], al, bh, acc[ni]);
                }
            }
            __syncthreads();   // sD free (previous epilogue done)

            #pragma unroll
            for (int ni = 0; ni < 2; ni++)
                wmma::store_matrix_sync(sD + (wr*16)*LDD + wn*32 + ni*16, acc[ni], LDD, wmma::mem_row_major);
            __syncthreads();

            {   // tanh + xhat-weighted partial reduction (4 groups x 16 rows)
                const int kq = t & 63, grp = t >> 6;
                float p0 = 0.f, p1 = 0.f, p2 = 0.f;
                #pragma unroll
                for (int r = 0; r < 16; r++) {
                    const int jl = grp*16 + r;
                    const int jj = qr*64 + jl;
                    const float c = tanhap(sD[jl*LDD + kq]);
                    p0 += c * sXh[jj*4+0];
                    p1 += c * sXh[jj*4+1];
                    p2 += c * sXh[jj*4+2];
                }
                const int pb = ((grp<<6) + kq)*3;
                sPart[pb+0] = p0; sPart[pb+1] = p1; sPart[pb+2] = p2;
            }
            __syncthreads();
            if (t < 192) {
                const int kl = t/3, dd = t - kl*3;
                float s = sPart[kl*3+dd] + sPart[(64+kl)*3+dd]
                        + sPart[(128+kl)*3+dd] + sPart[(192+kl)*3+dd];
                s *= (1.f/NN);
                const int ci = (q*64 + kl)*3 + dd;
                if (qr == 0) sComb[ci] = s; else sComb[ci] += s;
            }
            __syncthreads();
        }
    }

    // ---- node tail ----
    {
        const float c0 = sComb[t*3+0], c1 = sComb[t*3+1], c2 = sComb[t*3+2];
        sCn[t] = c0*c0 + c1*c1 + c2*c2;
    }
    __syncthreads();
    if (t < 64) {
        float a = b_p1[t];
        for (int c = 0; c < 256; c++) a += sCn[c]*W_p1[c*64 + t];
        sT1[t] = siluf(a);
    }
    __syncthreads();
    if (t < 64) {
        float a = b_p2[t];
        for (int c = 0; c < 64; c++) a += sT1[c]*W_p2[c*64 + t];
        sT2[t] = siluf(a);
    }
    __syncthreads();
    if (t < 64) {
        float a = b_n1[t];
        for (int r = 0; r < 64;  r++) a += sHi[r] *W_n1[r*64 + t];
        for (int r = 0; r < 256; r++) a += sHes[r]*W_n1[(64+r)*64 + t];
        for (int r = 0; r < 64;  r++) a += sT2[r] *W_n1[(320+r)*64 + t];
        sT1[t] = siluf(a);
    }
    __syncthreads();
    if (t < 64) {
        float a = b_n2[t];
        for (int c = 0; c < 64; c++) a += sT1[c]*W_n2[c*64 + t];
        const float hn = sHi[t] + siluf(a);
        sHn[t] = hn;
        out[(b*NN + i)*64 + t] = hn;
    }
    __syncthreads();
    if (t < 64) {
        float a = b_v1[t];
        for (int c = 0; c < 64; c++) a += sHn[c]*W_v1[c*64 + t];
        sT1[t] = siluf(a);
    }
    __syncthreads();
    if (w == 0) {
        float s = sT1[lane]*W_v2[lane] + sT1[lane+32]*W_v2[lane+32];
        #pragma unroll
        for (int o = 16; o; o >>= 1) s += __shfl_xor_sync(~0u, s, o);
        if (lane == 0) sMisc[0] = 2.f/(1.f + __expf(-s));
    }
    if (w >= 1 && w <= 3) {
        const int dd = w - 1;
        float s = 0.f;
        for (int q2 = 0; q2 < 8; q2++)
            s += sComb[(lane + 32*q2)*3 + dd]*W_vmix[lane + 32*q2];
        #pragma unroll
        for (int o = 16; o; o >>= 1) s += __shfl_xor_sync(~0u, s, o);
        if (lane == 0) sMisc[1+dd] = s;
    }
    __syncthreads();
    if (t < 3) {
        const float vn = sMisc[1+t] + sMisc[0]*v[(b*NN+i)*3 + t];
        const float xn = x[(b*NN+i)*3 + t] + vn;
        out[NB*NN*64 + (b*NN+i)*3 + t]           = xn;
        out[NB*NN*64 + NB*NN*3 + (b*NN+i)*3 + t] = vn;
    }
}

// ---------------------------------------------------------------------------
extern "C" void kernel_launch(void* const* d_in, const int* in_sizes, int n_in,
                              void* d_out, int out_size)
{
    const float* h      = (const float*)d_in[0];
    const float* x      = (const float*)d_in[1];
    const float* v      = (const float*)d_in[2];
    const float* W_in   = (const float*)d_in[3];
    const float* b_in   = (const float*)d_in[4];
    const float* means  = (const float*)d_in[5];
    const float* betas  = (const float*)d_in[6];
    const float* W_o1   = (const float*)d_in[7];
    const float* b_o1   = (const float*)d_in[8];
    const float* W_o2   = (const float*)d_in[9];
    const float* b_o2   = (const float*)d_in[10];
    const float* W_sem  = (const float*)d_in[11];
    const float* b_sem  = (const float*)d_in[12];
    const float* W_xmix = (const float*)d_in[13];
    const float* W_p1   = (const float*)d_in[14];
    const float* b_p1   = (const float*)d_in[15];
    const float* W_p2   = (const float*)d_in[16];
    const float* b_p2   = (const float*)d_in[17];
    const float* W_n1   = (const float*)d_in[18];
    const float* b_n1   = (const float*)d_in[19];
    const float* W_n2   = (const float*)d_in[20];
    const float* b_n2   = (const float*)d_in[21];
    const float* W_v1   = (const float*)d_in[22];
    const float* b_v1   = (const float*)d_in[23];
    const float* W_v2   = (const float*)d_in[24];
    const float* W_vmix = (const float*)d_in[25];
    float* out = (float*)d_out;

    const size_t smA = (size_t)(NN*65 + 128*NKF + DCAT*64 + 64*64 + 256
                                + 3*NKF + 2*64 + 8 + NN*3 + 4*NN + 16) * sizeof(float);
    const size_t smB = (size_t)(2*64*LDA + 2*256*LDB) * sizeof(__nv_bfloat16)
                     + (size_t)(64*LDD + 1024 + 768 + 256 + 768 + 4*64 + 256 + 16) * sizeof(float);

    cudaFuncSetAttribute(k_edge,    cudaFuncAttributeMaxDynamicSharedMemorySize, (int)smA);
    cudaFuncSetAttribute(k_spatial, cudaFuncAttributeMaxDynamicSharedMemorySize, (int)smB);

    k_prep<<<NC, NC>>>(W_xmix);
    k_edge<<<NB*NN, 256, smA>>>(h, x, W_in, b_in, means, betas,
                                W_o1, b_o1, W_o2, b_o2, W_sem, b_sem);
    k_spatial<<<NB*NN, 256, smB>>>(h, x, v, W_p1, b_p1, W_p2, b_p2,
                                   W_n1, b_n1, W_n2, b_n2, W_v1, b_v1,
                                   W_v2, W_vmix, out);
}